// round 4
// baseline (speedup 1.0000x reference)
#include <cuda_runtime.h>
#include <math.h>

#define DIMS   20
#define MULTK  8
#define KCOMP  168
#define NFEAT  40              // [x^2 (20), x (20)]
#define NPAIR  (NFEAT/2)       // 20 f32x2 pairs
#define LOG2E  1.4426950408889634f
#define LN2    0.6931471805599453f
#define LOGNRM (-18.378770664093453f)   // -(DIMS/2)*log(2*pi)
#define NTOT   524288
#define TPB    256

// Precomputed coefficients (log2-domain): W[k][0..19] = -0.5*inv*log2e (x^2),
// W[k][20..39] = mu*inv*log2e (x), c[k] = (log w_k + 0.5*(20-i)*ln10 - 0.5*sum mu^2 inv)*log2e
__device__ float g_W[KCOMP * NFEAT];
__device__ float g_c[KCOMP];

// ---------------- packed f32x2 helpers ----------------
__device__ __forceinline__ unsigned long long pack2(float lo, float hi) {
    unsigned long long r;
    asm("mov.b64 %0, {%1, %2};" : "=l"(r) : "f"(lo), "f"(hi));
    return r;
}
__device__ __forceinline__ void unpack2(unsigned long long v, float& lo, float& hi) {
    asm("mov.b64 {%0, %1}, %2;" : "=f"(lo), "=f"(hi) : "l"(v));
}
__device__ __forceinline__ unsigned long long fma2(unsigned long long a,
                                                   unsigned long long b,
                                                   unsigned long long c) {
    unsigned long long d;
    asm("fma.rn.f32x2 %0, %1, %2, %3;" : "=l"(d) : "l"(a), "l"(b), "l"(c));
    return d;
}
__device__ __forceinline__ unsigned long long add2(unsigned long long a,
                                                   unsigned long long b) {
    unsigned long long d;
    asm("add.rn.f32x2 %0, %1, %2;" : "=l"(d) : "l"(a), "l"(b));
    return d;
}
__device__ __forceinline__ float ex2f(float x) {
    float r;
    asm("ex2.approx.f32 %0, %1;" : "=f"(r) : "f"(x));
    return r;
}
__device__ __forceinline__ float lg2f(float x) {
    float r;
    asm("lg2.approx.f32 %0, %1;" : "=f"(r) : "f"(x));
    return r;
}

// ---------------- prep: softmax(alpha) + coefficient matrix ----------------
__global__ void gmm_prep(const float* __restrict__ alpha,
                         const float* __restrict__ mu,
                         const float* __restrict__ cov) {
    __shared__ float s_red[TPB];
    __shared__ float s_exp[KCOMP];
    int tid = threadIdx.x;

    float a = (tid < KCOMP) ? alpha[tid] : -1e30f;
    s_red[tid] = a;
    __syncthreads();
    for (int s = TPB / 2; s > 0; s >>= 1) {
        if (tid < s) s_red[tid] = fmaxf(s_red[tid], s_red[tid + s]);
        __syncthreads();
    }
    float amax = s_red[0];
    __syncthreads();

    float e = (tid < KCOMP) ? expf(a - amax) : 0.0f;
    if (tid < KCOMP) s_exp[tid] = e;
    s_red[tid] = e;
    __syncthreads();
    for (int s = TPB / 2; s > 0; s >>= 1) {
        if (tid < s) s_red[tid] += s_red[tid + s];
        __syncthreads();
    }
    float sum = s_red[0];

    if (tid < KCOMP) {
        int k = tid;
        int i = k / MULTK;
        float logw = logf(s_exp[k] / sum);
        // det_cov = var^i * 0.1^(DIMS-i), var = EPS^2 = 1 -> log(sig_term) = 0.5*(DIMS-i)*ln(10)
        float lsig = 0.5f * (float)(DIMS - i) * 2.302585092994046f;
        float cacc = logw + lsig;
        #pragma unroll
        for (int d = 0; d < DIMS; ++d) {
            float inv = 1.0f / cov[k * DIMS + d];   // scale = var = 1
            float m = mu[k * DIMS + d];
            g_W[k * NFEAT + d]        = -0.5f * inv * LOG2E;
            g_W[k * NFEAT + DIMS + d] = m * inv * LOG2E;
            cacc -= 0.5f * m * m * inv;
        }
        g_c[k] = cacc * LOG2E;
    }
}

// ---------------- main: one thread per sample ----------------
__global__ __launch_bounds__(TPB) void gmm_main(const float* __restrict__ sample,
                                                float* __restrict__ out,
                                                int n_total) {
    __shared__ __align__(16) float sW[KCOMP * NFEAT];
    __shared__ float sc[KCOMP];
    int tid = threadIdx.x;
    for (int idx = tid; idx < KCOMP * NFEAT; idx += TPB) sW[idx] = g_W[idx];
    if (tid < KCOMP) sc[tid] = g_c[tid];
    __syncthreads();

    int n = blockIdx.x * TPB + tid;
    if (n >= n_total) return;

    // 20 floats per row, 80B row stride -> 16B aligned, 5x float4
    const float4* xp = (const float4*)(sample + (size_t)n * DIMS);
    float x[DIMS];
    #pragma unroll
    for (int j = 0; j < 5; ++j) {
        float4 v = xp[j];
        x[4 * j + 0] = v.x; x[4 * j + 1] = v.y;
        x[4 * j + 2] = v.z; x[4 * j + 3] = v.w;
    }

    // packed feature vector: fv[0..9] = x^2 pairs, fv[10..19] = x pairs
    unsigned long long fv[NPAIR];
    #pragma unroll
    for (int j = 0; j < 10; ++j)
        fv[j] = pack2(x[2 * j] * x[2 * j], x[2 * j + 1] * x[2 * j + 1]);
    #pragma unroll
    for (int j = 0; j < 10; ++j)
        fv[10 + j] = pack2(x[2 * j], x[2 * j + 1]);

    float dens0 = 0.0f, dens1 = 0.0f;
    #pragma unroll 2
    for (int k = 0; k < KCOMP; ++k) {
        const ulonglong2* wrow = (const ulonglong2*)(sW + k * NFEAT);
        unsigned long long a0 = 0ULL, a1 = 0ULL, a2 = 0ULL, a3 = 0ULL;
        #pragma unroll
        for (int j = 0; j < 10; j += 2) {
            ulonglong2 w0 = wrow[j];       // LDS.128: coeff pairs 2j, 2j+1
            ulonglong2 w1 = wrow[j + 1];
            a0 = fma2(fv[2 * j + 0], w0.x, a0);
            a1 = fma2(fv[2 * j + 1], w0.y, a1);
            a2 = fma2(fv[2 * j + 2], w1.x, a2);
            a3 = fma2(fv[2 * j + 3], w1.y, a3);
        }
        a0 = add2(a0, a2);
        a1 = add2(a1, a3);
        a0 = add2(a0, a1);
        float lo, hi;
        unpack2(a0, lo, hi);
        float t = lo + hi + sc[k];
        float ek = ex2f(t);             // exp(e) since coeffs carry log2(e)
        if (k & 1) dens1 += ek; else dens0 += ek;
    }
    float density = dens0 + dens1;
    out[n] = lg2f(density) * LN2 + LOGNRM;
}

extern "C" void kernel_launch(void* const* d_in, const int* in_sizes, int n_in,
                              void* d_out, int out_size) {
    const float* sample = (const float*)d_in[0];
    const float* alpha  = (const float*)d_in[1];
    const float* mu     = (const float*)d_in[2];
    const float* cov    = (const float*)d_in[3];
    float* out = (float*)d_out;
    int n_total = in_sizes[0] / DIMS;

    gmm_prep<<<1, TPB>>>(alpha, mu, cov);
    gmm_main<<<(n_total + TPB - 1) / TPB, TPB>>>(sample, out, n_total);
}

// round 5
// speedup vs baseline: 1.3138x; 1.3138x over previous
#include <cuda_runtime.h>
#include <math.h>

#define DIMS   20
#define MULTK  8
#define KCOMP  168
#define LOG2E  1.4426950408889634f
#define LN2    0.6931471805599453f
#define LOGNRM (-18.378770664093453f)   // -(DIMS/2)*log(2*pi)
#define TPB    128
#define SPT    4                        // samples per thread

// prep outputs
__device__ unsigned long long g_Wdup[KCOMP * DIMS];  // (w1_kd, w1_kd) pairs, w1 = mu*inv*log2e
__device__ unsigned long long g_cdup[KCOMP];         // (c_k, c_k)
__device__ float g_w2c[DIMS];                        // common x^2 coeff row (-0.5*inv*log2e), from k=0
__device__ float g_Wg[KCOMP * 2 * DIMS];             // general path: [x^2 coeffs | x coeffs]
__device__ int   g_flag;                             // 1 if cov rows identical across k

// ---------------- packed f32x2 helpers ----------------
__device__ __forceinline__ unsigned long long pack2(float lo, float hi) {
    unsigned long long r;
    asm("mov.b64 %0, {%1, %2};" : "=l"(r) : "f"(lo), "f"(hi));
    return r;
}
__device__ __forceinline__ void unpack2(unsigned long long v, float& lo, float& hi) {
    asm("mov.b64 {%0, %1}, %2;" : "=f"(lo), "=f"(hi) : "l"(v));
}
__device__ __forceinline__ unsigned long long fma2(unsigned long long a,
                                                   unsigned long long b,
                                                   unsigned long long c) {
    unsigned long long d;
    asm("fma.rn.f32x2 %0, %1, %2, %3;" : "=l"(d) : "l"(a), "l"(b), "l"(c));
    return d;
}
__device__ __forceinline__ unsigned long long add2(unsigned long long a,
                                                   unsigned long long b) {
    unsigned long long d;
    asm("add.rn.f32x2 %0, %1, %2;" : "=l"(d) : "l"(a), "l"(b));
    return d;
}
__device__ __forceinline__ float ex2f(float x) {
    float r;
    asm("ex2.approx.f32 %0, %1;" : "=f"(r) : "f"(x));
    return r;
}
__device__ __forceinline__ float lg2f(float x) {
    float r;
    asm("lg2.approx.f32 %0, %1;" : "=f"(r) : "f"(x));
    return r;
}

// ---------------- prep: softmax(alpha) + coefficient matrices ----------------
__global__ void gmm_prep(const float* __restrict__ alpha,
                         const float* __restrict__ mu,
                         const float* __restrict__ cov) {
    __shared__ float s_red[256];
    __shared__ float s_exp[KCOMP];
    __shared__ int   s_ok[256];
    int tid = threadIdx.x;

    float a = (tid < KCOMP) ? alpha[tid] : -1e30f;
    s_red[tid] = a;
    __syncthreads();
    for (int s = 128; s > 0; s >>= 1) {
        if (tid < s) s_red[tid] = fmaxf(s_red[tid], s_red[tid + s]);
        __syncthreads();
    }
    float amax = s_red[0];
    __syncthreads();

    float e = (tid < KCOMP) ? expf(a - amax) : 0.0f;
    if (tid < KCOMP) s_exp[tid] = e;
    s_red[tid] = e;
    __syncthreads();
    for (int s = 128; s > 0; s >>= 1) {
        if (tid < s) s_red[tid] += s_red[tid + s];
        __syncthreads();
    }
    float sum = s_red[0];

    // uniform-cov check: every component's cov row bitwise equals row 0
    int ok = 1;
    if (tid < KCOMP) {
        for (int d = 0; d < DIMS; ++d)
            ok &= (__float_as_int(cov[tid * DIMS + d]) == __float_as_int(cov[d]));
    }
    s_ok[tid] = ok;
    __syncthreads();
    for (int s = 128; s > 0; s >>= 1) {
        if (tid < s) s_ok[tid] &= s_ok[tid + s];
        __syncthreads();
    }
    if (tid == 0) g_flag = s_ok[0];

    if (tid < KCOMP) {
        int k = tid;
        int i = k / MULTK;
        float logw = logf(s_exp[k] / sum);
        // det_cov = var^i * 0.1^(DIMS-i); var = EPS^2 = 1 -> log(sig_term)=0.5*(DIMS-i)*ln(10)
        float lsig = 0.5f * (float)(DIMS - i) * 2.302585092994046f;
        float cacc = logw + lsig;
        #pragma unroll
        for (int d = 0; d < DIMS; ++d) {
            float inv = 1.0f / cov[k * DIMS + d];   // scale = var = 1
            float m = mu[k * DIMS + d];
            float w2 = -0.5f * inv * LOG2E;
            float w1 = m * inv * LOG2E;
            g_Wg[k * 2 * DIMS + d]        = w2;
            g_Wg[k * 2 * DIMS + DIMS + d] = w1;
            g_Wdup[k * DIMS + d] = pack2(w1, w1);
            if (k == 0) g_w2c[d] = w2;
            cacc -= 0.5f * m * m * inv;
        }
        float ck = cacc * LOG2E;
        g_cdup[k] = pack2(ck, ck);
    }
}

// ---------------- main: 4 samples per thread, sample-pair packed ----------------
__global__ __launch_bounds__(TPB, 4) void gmm_main(const float* __restrict__ sample,
                                                   float* __restrict__ out,
                                                   int n_total) {
    __shared__ __align__(16) unsigned long long sWd[KCOMP * DIMS];  // 26.25KB; general path aliases as float[K*40]
    __shared__ unsigned long long sCd[KCOMP];
    __shared__ float sw2c[DIMS];
    int tid = threadIdx.x;

    int flag = g_flag;
    if (flag) {
        for (int i = tid; i < KCOMP * DIMS; i += TPB) sWd[i] = g_Wdup[i];
    } else {
        float* sf = (float*)sWd;
        for (int i = tid; i < KCOMP * 2 * DIMS; i += TPB) sf[i] = g_Wg[i];
    }
    for (int i = tid; i < KCOMP; i += TPB) sCd[i] = g_cdup[i];
    if (tid < DIMS) sw2c[tid] = g_w2c[tid];
    __syncthreads();

    int base = blockIdx.x * (TPB * SPT) + tid;
    int n0 = base, n1 = base + TPB, n2 = base + 2 * TPB, n3 = base + 3 * TPB;
    int m0 = min(n0, n_total - 1), m1 = min(n1, n_total - 1);
    int m2 = min(n2, n_total - 1), m3 = min(n3, n_total - 1);

    // load 4 sample rows (20 floats each, 16B-aligned rows: 5x float4)
    float x0[DIMS], x1[DIMS], x2[DIMS], x3[DIMS];
    {
        const float4* p0 = (const float4*)(sample + (size_t)m0 * DIMS);
        const float4* p1 = (const float4*)(sample + (size_t)m1 * DIMS);
        const float4* p2 = (const float4*)(sample + (size_t)m2 * DIMS);
        const float4* p3 = (const float4*)(sample + (size_t)m3 * DIMS);
        #pragma unroll
        for (int j = 0; j < 5; ++j) {
            float4 v0 = p0[j], v1 = p1[j], v2 = p2[j], v3 = p3[j];
            x0[4*j+0]=v0.x; x0[4*j+1]=v0.y; x0[4*j+2]=v0.z; x0[4*j+3]=v0.w;
            x1[4*j+0]=v1.x; x1[4*j+1]=v1.y; x1[4*j+2]=v1.z; x1[4*j+3]=v1.w;
            x2[4*j+0]=v2.x; x2[4*j+1]=v2.y; x2[4*j+2]=v2.z; x2[4*j+3]=v2.w;
            x3[4*j+0]=v3.x; x3[4*j+1]=v3.y; x3[4*j+2]=v3.z; x3[4*j+3]=v3.w;
        }
    }

    float d0 = 0.0f, d1 = 0.0f, d2 = 0.0f, d3 = 0.0f;

    if (flag) {
        // ---- fast path: x^2 coefficients uniform across k ----
        // q2_s = sum_d w2c_d * x_sd^2, computed once per sample
        float q0 = 0.f, q1 = 0.f, q2s = 0.f, q3 = 0.f;
        #pragma unroll
        for (int d = 0; d < DIMS; ++d) {
            float w = sw2c[d];
            q0 = fmaf(w * x0[d], x0[d], q0);
            q1 = fmaf(w * x1[d], x1[d], q1);
            q2s = fmaf(w * x2[d], x2[d], q2s);
            q3 = fmaf(w * x3[d], x3[d], q3);
        }
        unsigned long long q01 = pack2(q0, q1);
        unsigned long long q23 = pack2(q2s, q3);

        // packed features: two samples per f32x2 register
        unsigned long long fp01[DIMS], fp23[DIMS];
        #pragma unroll
        for (int d = 0; d < DIMS; ++d) {
            fp01[d] = pack2(x0[d], x1[d]);
            fp23[d] = pack2(x2[d], x3[d]);
        }

        #pragma unroll 2
        for (int k = 0; k < KCOMP; ++k) {
            const ulonglong2* w = (const ulonglong2*)(sWd + k * DIMS);
            unsigned long long cd = sCd[k];
            ulonglong2 w0 = w[0];
            // fold q2 and c_k into the two chain inits (free addends)
            unsigned long long a0 = fma2(fp01[0], w0.x, q01);
            unsigned long long a1 = fma2(fp01[1], w0.y, cd);
            unsigned long long b0 = fma2(fp23[0], w0.x, q23);
            unsigned long long b1 = fma2(fp23[1], w0.y, cd);
            #pragma unroll
            for (int j = 1; j < DIMS / 2; ++j) {
                ulonglong2 ww = w[j];
                a0 = fma2(fp01[2*j],   ww.x, a0);
                a1 = fma2(fp01[2*j+1], ww.y, a1);
                b0 = fma2(fp23[2*j],   ww.x, b0);
                b1 = fma2(fp23[2*j+1], ww.y, b1);
            }
            unsigned long long t01 = add2(a0, a1);
            unsigned long long t23 = add2(b0, b1);
            float u0, u1, u2, u3;
            unpack2(t01, u0, u1);
            unpack2(t23, u2, u3);
            d0 += ex2f(u0);
            d1 += ex2f(u1);
            d2 += ex2f(u2);
            d3 += ex2f(u3);
        }
    } else {
        // ---- general fallback: scalar per-sample, full 40-feature rows ----
        const float* sf = (const float*)sWd;
        for (int k = 0; k < KCOMP; ++k) {
            const float* wr = sf + k * 2 * DIMS;
            float clo, chi;
            unpack2(sCd[k], clo, chi);
            float e0 = clo, e1 = clo, e2 = clo, e3 = clo;
            (void)chi;
            #pragma unroll
            for (int d = 0; d < DIMS; ++d) {
                float w2 = wr[d], w1 = wr[DIMS + d];
                e0 = fmaf(w2 * x0[d], x0[d], fmaf(w1, x0[d], e0));
                e1 = fmaf(w2 * x1[d], x1[d], fmaf(w1, x1[d], e1));
                e2 = fmaf(w2 * x2[d], x2[d], fmaf(w1, x2[d], e2));
                e3 = fmaf(w2 * x3[d], x3[d], fmaf(w1, x3[d], e3));
            }
            d0 += ex2f(e0);
            d1 += ex2f(e1);
            d2 += ex2f(e2);
            d3 += ex2f(e3);
        }
    }

    if (n0 < n_total) out[n0] = lg2f(d0) * LN2 + LOGNRM;
    if (n1 < n_total) out[n1] = lg2f(d1) * LN2 + LOGNRM;
    if (n2 < n_total) out[n2] = lg2f(d2) * LN2 + LOGNRM;
    if (n3 < n_total) out[n3] = lg2f(d3) * LN2 + LOGNRM;
}

extern "C" void kernel_launch(void* const* d_in, const int* in_sizes, int n_in,
                              void* d_out, int out_size) {
    const float* sample = (const float*)d_in[0];
    const float* alpha  = (const float*)d_in[1];
    const float* mu     = (const float*)d_in[2];
    const float* cov    = (const float*)d_in[3];
    float* out = (float*)d_out;
    int n_total = in_sizes[0] / DIMS;

    gmm_prep<<<1, 256>>>(alpha, mu, cov);
    int per_block = TPB * SPT;
    gmm_main<<<(n_total + per_block - 1) / per_block, TPB>>>(sample, out, n_total);
}

// round 8
// speedup vs baseline: 3.1833x; 2.4229x over previous
#include <cuda_runtime.h>
#include <cuda_bf16.h>
#include <math.h>

#define DIMS   20
#define MULTK  8
#define KCOMP  168
#define LOG2E  1.4426950408889634f
#define LN2    0.6931471805599453f
#define LOGNRM (-18.378770664093453f)   // -(DIMS/2)*log(2*pi)

#define TILE_M 128
#define KF     64          // GEMM K: [x_hi(20) | x_hi(20) | x_lo(20) | 0(4)]
#define NTILES 21          // 168 / 8 components per n-tile
#define TPB    128
#define AS     72          // smem row stride in bf16 (144B -> conflict-free ldmatrix)

// prep outputs
__device__ __align__(16) unsigned short g_B[KCOMP * KF];  // bf16 bits, row k = [W_hi|W_lo|W_hi|0]
__device__ float g_c[KCOMP];              // log2-domain constant per component
__device__ float g_w2c[DIMS];             // common x^2 coeff row (-0.5*inv*log2e)
__device__ float g_Wg[KCOMP * 2 * DIMS];  // fallback coeffs (log2-domain)
__device__ int   g_flag;                  // 1 if cov rows identical across k

// ---------------- helpers ----------------
__device__ __forceinline__ float ex2f(float x) { float r; asm("ex2.approx.f32 %0, %1;" : "=f"(r) : "f"(x)); return r; }
__device__ __forceinline__ float lg2f(float x) { float r; asm("lg2.approx.f32 %0, %1;" : "=f"(r) : "f"(x)); return r; }
__device__ __forceinline__ unsigned smem_u32(const void* p) {
    unsigned a;
    asm("{ .reg .u64 t; cvta.to.shared.u64 t, %1; cvt.u32.u64 %0, t; }" : "=r"(a) : "l"(p));
    return a;
}
__device__ __forceinline__ void ldsm_x4(unsigned& r0, unsigned& r1, unsigned& r2, unsigned& r3, unsigned addr) {
    asm volatile("ldmatrix.sync.aligned.m8n8.x4.shared.b16 {%0,%1,%2,%3}, [%4];"
                 : "=r"(r0), "=r"(r1), "=r"(r2), "=r"(r3) : "r"(addr));
}
__device__ __forceinline__ void mma16816(float* d, const unsigned* a, unsigned b0, unsigned b1) {
    asm volatile("mma.sync.aligned.m16n8k16.row.col.f32.bf16.bf16.f32 "
                 "{%0,%1,%2,%3}, {%4,%5,%6,%7}, {%8,%9}, {%0,%1,%2,%3};"
                 : "+f"(d[0]), "+f"(d[1]), "+f"(d[2]), "+f"(d[3])
                 : "r"(a[0]), "r"(a[1]), "r"(a[2]), "r"(a[3]), "r"(b0), "r"(b1));
}

// ---------------- prep: softmax(alpha) + coefficient matrices ----------------
__global__ void gmm_prep(const float* __restrict__ alpha,
                         const float* __restrict__ mu,
                         const float* __restrict__ cov) {
    __shared__ float s_red[256];
    __shared__ float s_exp[KCOMP];
    __shared__ int   s_ok[256];
    int tid = threadIdx.x;

    float a = (tid < KCOMP) ? alpha[tid] : -1e30f;
    s_red[tid] = a;
    __syncthreads();
    for (int s = 128; s > 0; s >>= 1) {
        if (tid < s) s_red[tid] = fmaxf(s_red[tid], s_red[tid + s]);
        __syncthreads();
    }
    float amax = s_red[0];
    __syncthreads();

    float e = (tid < KCOMP) ? expf(a - amax) : 0.0f;
    if (tid < KCOMP) s_exp[tid] = e;
    s_red[tid] = e;
    __syncthreads();
    for (int s = 128; s > 0; s >>= 1) {
        if (tid < s) s_red[tid] += s_red[tid + s];
        __syncthreads();
    }
    float sum = s_red[0];

    // uniform-cov check (bitwise vs row 0)
    int ok = 1;
    if (tid < KCOMP) {
        for (int d = 0; d < DIMS; ++d)
            ok &= (__float_as_int(cov[tid * DIMS + d]) == __float_as_int(cov[d]));
    }
    s_ok[tid] = ok;
    __syncthreads();
    for (int s = 128; s > 0; s >>= 1) {
        if (tid < s) s_ok[tid] &= s_ok[tid + s];
        __syncthreads();
    }
    if (tid == 0) g_flag = s_ok[0];

    if (tid < KCOMP) {
        int k = tid;
        int i = k / MULTK;
        float logw = logf(s_exp[k] / sum);
        // det_cov = var^i * 0.1^(DIMS-i); var = EPS^2 = 1 -> log(sig)=0.5*(DIMS-i)*ln(10)
        float lsig = 0.5f * (float)(DIMS - i) * 2.302585092994046f;
        float cacc = logw + lsig;
        #pragma unroll
        for (int d = 0; d < DIMS; ++d) {
            float inv = 1.0f / cov[k * DIMS + d];
            float m = mu[k * DIMS + d];
            float w2 = -0.5f * inv * LOG2E;
            float w1 = m * inv * LOG2E;
            g_Wg[k * 2 * DIMS + d]        = w2;
            g_Wg[k * 2 * DIMS + DIMS + d] = w1;
            if (k == 0) g_w2c[d] = w2;
            __nv_bfloat16 h = __float2bfloat16_rn(w1);
            float lo = w1 - __bfloat162float(h);
            __nv_bfloat16 l = __float2bfloat16_rn(lo);
            g_B[k * KF + d]            = __bfloat16_as_ushort(h);   // pairs x_hi
            g_B[k * KF + DIMS + d]     = __bfloat16_as_ushort(l);   // pairs x_hi
            g_B[k * KF + 2 * DIMS + d] = __bfloat16_as_ushort(h);   // pairs x_lo
            cacc -= 0.5f * m * m * inv;
        }
        #pragma unroll
        for (int cpad = 3 * DIMS; cpad < KF; ++cpad) g_B[k * KF + cpad] = 0;
        g_c[k] = cacc * LOG2E;
    }
}

// ---------------- tensor main: mma.sync bf16 (uniform-cov fast path) ----------------
__global__ __launch_bounds__(TPB) void gmm_tensor(const float* __restrict__ sample,
                                                  float* __restrict__ out,
                                                  int n_total) {
    if (g_flag == 0) return;   // handled by gmm_general

    __shared__ __align__(16) unsigned short sA[TILE_M * AS];   // 18432 B
    __shared__ __align__(16) unsigned short sB[KCOMP * AS];    // 24192 B
    __shared__ float s_sc[KCOMP];
    __shared__ float s_w2[DIMS];
    __shared__ float s_q2[TILE_M];

    int tid  = threadIdx.x;
    int wid  = tid >> 5;
    int lane = tid & 31;

    // ---- stage B, sc, w2c ----
    {
        const unsigned* Bsrc = (const unsigned*)g_B;   // rows of 32 u32
        for (int i = tid; i < KCOMP * (KF / 2); i += TPB) {
            int row = i >> 5, c = i & 31;
            ((unsigned*)sB)[row * (AS / 2) + c] = Bsrc[i];
        }
        for (int i = tid; i < KCOMP; i += TPB) s_sc[i] = g_c[i];
        if (tid < DIMS) s_w2[tid] = g_w2c[tid];
    }

    // ---- stage A: this thread's sample row, bf16 2-way split ----
    int n = blockIdx.x * TILE_M + tid;
    int m = min(n, n_total - 1);
    float x[DIMS];
    {
        const float4* xp = (const float4*)(sample + (size_t)m * DIMS);
        #pragma unroll
        for (int j = 0; j < 5; ++j) {
            float4 v = xp[j];
            x[4*j+0] = v.x; x[4*j+1] = v.y; x[4*j+2] = v.z; x[4*j+3] = v.w;
        }
    }
    {
        unsigned* Arow = (unsigned*)sA + tid * (AS / 2);
        #pragma unroll
        for (int j = 0; j < 10; ++j) {
            __nv_bfloat16 h0 = __float2bfloat16_rn(x[2*j]);
            __nv_bfloat16 h1 = __float2bfloat16_rn(x[2*j+1]);
            float r0 = x[2*j]   - __bfloat162float(h0);
            float r1 = x[2*j+1] - __bfloat162float(h1);
            __nv_bfloat16 l0 = __float2bfloat16_rn(r0);
            __nv_bfloat16 l1 = __float2bfloat16_rn(r1);
            unsigned hh = (unsigned)__bfloat16_as_ushort(h0) | ((unsigned)__bfloat16_as_ushort(h1) << 16);
            unsigned ll = (unsigned)__bfloat16_as_ushort(l0) | ((unsigned)__bfloat16_as_ushort(l1) << 16);
            Arow[j] = hh; Arow[10 + j] = hh; Arow[20 + j] = ll;
        }
        Arow[30] = 0u; Arow[31] = 0u;
    }
    __syncthreads();

    // ---- q2 for this thread's row ----
    {
        float q2 = 0.0f;
        #pragma unroll
        for (int d = 0; d < DIMS; ++d) q2 = fmaf(s_w2[d] * x[d], x[d], q2);
        s_q2[tid] = q2;
    }
    __syncthreads();

    unsigned sAu = smem_u32(sA);
    unsigned sBu = smem_u32(sB);

    // ---- load A fragments for this warp's 2 m-tiles (rows wid*32 .. +31) ----
    int lr = lane & 7;           // row within 8x8 tile
    int tI = lane >> 3;          // tile index 0..3
    int arow_off = lr + (tI & 1) * 8;
    int akcol_off = (tI >> 1) * 8;

    unsigned aF0[16], aF1[16];   // [ks][4]
    int R0 = wid * 32;
    #pragma unroll
    for (int ks = 0; ks < 4; ++ks) {
        unsigned ad0 = sAu + (unsigned)((R0 + arow_off) * AS + ks * 16 + akcol_off) * 2u;
        unsigned ad1 = sAu + (unsigned)((R0 + 16 + arow_off) * AS + ks * 16 + akcol_off) * 2u;
        ldsm_x4(aF0[4*ks], aF0[4*ks+1], aF0[4*ks+2], aF0[4*ks+3], ad0);
        ldsm_x4(aF1[4*ks], aF1[4*ks+1], aF1[4*ks+2], aF1[4*ks+3], ad1);
    }

    float dl0 = 0.f, dh0 = 0.f, dl1 = 0.f, dh1 = 0.f;
    int t4 = lane & 3;

    #pragma unroll 3
    for (int nb = 0; nb < NTILES; ++nb) {
        // B fragments: rows = comps 8nb..8nb+7, k chunks 0-31 / 32-63
        unsigned b[8];
        unsigned brow = (unsigned)(8 * nb + lr) * AS;
        ldsm_x4(b[0], b[1], b[2], b[3], sBu + (brow + (unsigned)tI * 8u) * 2u);
        ldsm_x4(b[4], b[5], b[6], b[7], sBu + (brow + 32u + (unsigned)tI * 8u) * 2u);

        float a0[4] = {0.f, 0.f, 0.f, 0.f};
        float a1[4] = {0.f, 0.f, 0.f, 0.f};
        #pragma unroll
        for (int ks = 0; ks < 4; ++ks) {
            mma16816(a0, &aF0[4*ks], b[2*ks], b[2*ks+1]);
            mma16816(a1, &aF1[4*ks], b[2*ks], b[2*ks+1]);
        }
        float c0 = s_sc[nb * 8 + 2 * t4];
        float c1 = s_sc[nb * 8 + 2 * t4 + 1];
        dl0 += ex2f(a0[0] + c0) + ex2f(a0[1] + c1);
        dh0 += ex2f(a0[2] + c0) + ex2f(a0[3] + c1);
        dl1 += ex2f(a1[0] + c0) + ex2f(a1[1] + c1);
        dh1 += ex2f(a1[2] + c0) + ex2f(a1[3] + c1);
    }

    // quad reduce (cols of a row live on lanes with same lane/4)
    #pragma unroll
    for (int msk = 1; msk <= 2; msk <<= 1) {
        dl0 += __shfl_xor_sync(0xffffffffu, dl0, msk);
        dh0 += __shfl_xor_sync(0xffffffffu, dh0, msk);
        dl1 += __shfl_xor_sync(0xffffffffu, dl1, msk);
        dh1 += __shfl_xor_sync(0xffffffffu, dh1, msk);
    }

    if (t4 == 0) {
        int g = lane >> 2;
        int base = blockIdx.x * TILE_M;
        int r0 = R0 + g, r1 = R0 + 8 + g, r2 = R0 + 16 + g, r3 = R0 + 24 + g;
        if (base + r0 < n_total) out[base + r0] = (lg2f(dl0) + s_q2[r0]) * LN2 + LOGNRM;
        if (base + r1 < n_total) out[base + r1] = (lg2f(dh0) + s_q2[r1]) * LN2 + LOGNRM;
        if (base + r2 < n_total) out[base + r2] = (lg2f(dl1) + s_q2[r2]) * LN2 + LOGNRM;
        if (base + r3 < n_total) out[base + r3] = (lg2f(dh1) + s_q2[r3]) * LN2 + LOGNRM;
    }
}

// ---------------- scalar fallback (non-uniform cov; dormant in practice) ----------------
__global__ void gmm_general(const float* __restrict__ sample,
                            float* __restrict__ out, int n_total) {
    if (g_flag != 0) return;
    __shared__ float sW[KCOMP * 2 * DIMS];
    __shared__ float sc[KCOMP];
    int tid = threadIdx.x;
    for (int i = tid; i < KCOMP * 2 * DIMS; i += blockDim.x) sW[i] = g_Wg[i];
    for (int i = tid; i < KCOMP; i += blockDim.x) sc[i] = g_c[i];
    __syncthreads();
    for (int n = blockIdx.x * blockDim.x + tid; n < n_total; n += gridDim.x * blockDim.x) {
        float x[DIMS];
        const float4* xp = (const float4*)(sample + (size_t)n * DIMS);
        #pragma unroll
        for (int j = 0; j < 5; ++j) {
            float4 v = xp[j];
            x[4*j+0]=v.x; x[4*j+1]=v.y; x[4*j+2]=v.z; x[4*j+3]=v.w;
        }
        float dens = 0.0f;
        for (int k = 0; k < KCOMP; ++k) {
            const float* wr = sW + k * 2 * DIMS;
            float e = sc[k];
            #pragma unroll
            for (int d = 0; d < DIMS; ++d)
                e = fmaf(wr[d] * x[d], x[d], fmaf(wr[DIMS + d], x[d], e));
            dens += ex2f(e);
        }
        out[n] = lg2f(dens) * LN2 + LOGNRM;
    }
}

extern "C" void kernel_launch(void* const* d_in, const int* in_sizes, int n_in,
                              void* d_out, int out_size) {
    const float* sample = (const float*)d_in[0];
    const float* alpha  = (const float*)d_in[1];
    const float* mu     = (const float*)d_in[2];
    const float* cov    = (const float*)d_in[3];
    float* out = (float*)d_out;
    int n_total = in_sizes[0] / DIMS;
    int ntiles = (n_total + TILE_M - 1) / TILE_M;

    gmm_prep<<<1, 256>>>(alpha, mu, cov);
    gmm_tensor<<<ntiles, TPB>>>(sample, out, n_total);
    gmm_general<<<296, 256>>>(sample, out, n_total);
}

// round 9
// speedup vs baseline: 3.5000x; 1.0995x over previous
#include <cuda_runtime.h>
#include <cuda_bf16.h>
#include <math.h>

#define DIMS   20
#define MULTK  8
#define KCOMP  168
#define LOG2E  1.4426950408889634f
#define LN2    0.6931471805599453f
#define LOGNRM (-18.378770664093453f)   // -(DIMS/2)*log(2*pi)

#define TILE_M 128
#define KF     64          // GEMM K: [x_hi(20) | x_hi(20) | x_lo(20) | 0(4)]
#define NTILES 21          // 168 / 8 components per n-tile
#define TPB    128
#define AS     72          // smem row stride in bf16 (144B -> conflict-free ldmatrix)

// prep outputs
__device__ __align__(16) unsigned short g_B[KCOMP * KF];  // bf16 bits, row k = [W_hi|W_lo|W_hi|0]
__device__ float g_c[KCOMP];              // log2-domain constant per component
__device__ float g_w2c[DIMS];             // common x^2 coeff row (-0.5*inv*log2e)
__device__ float g_Wg[KCOMP * 2 * DIMS];  // fallback coeffs (log2-domain)
__device__ int   g_flag;                  // 1 if cov rows identical across k

// ---------------- helpers ----------------
__device__ __forceinline__ float ex2f(float x) { float r; asm("ex2.approx.f32 %0, %1;" : "=f"(r) : "f"(x)); return r; }
__device__ __forceinline__ float lg2f(float x) { float r; asm("lg2.approx.f32 %0, %1;" : "=f"(r) : "f"(x)); return r; }
__device__ __forceinline__ unsigned smem_u32(const void* p) {
    unsigned a;
    asm("{ .reg .u64 t; cvta.to.shared.u64 t, %1; cvt.u32.u64 %0, t; }" : "=r"(a) : "l"(p));
    return a;
}
__device__ __forceinline__ void ldsm_x4(unsigned& r0, unsigned& r1, unsigned& r2, unsigned& r3, unsigned addr) {
    asm volatile("ldmatrix.sync.aligned.m8n8.x4.shared.b16 {%0,%1,%2,%3}, [%4];"
                 : "=r"(r0), "=r"(r1), "=r"(r2), "=r"(r3) : "r"(addr));
}
__device__ __forceinline__ void mma16816(float* d, const unsigned* a, unsigned b0, unsigned b1) {
    asm volatile("mma.sync.aligned.m16n8k16.row.col.f32.bf16.bf16.f32 "
                 "{%0,%1,%2,%3}, {%4,%5,%6,%7}, {%8,%9}, {%0,%1,%2,%3};"
                 : "+f"(d[0]), "+f"(d[1]), "+f"(d[2]), "+f"(d[3])
                 : "r"(a[0]), "r"(a[1]), "r"(a[2]), "r"(a[3]), "r"(b0), "r"(b1));
}

// ---------------- prep: fast softmax + coefficient build (1 block, 256 thr) ----------------
__global__ void gmm_prep(const float* __restrict__ alpha,
                         const float* __restrict__ mu,
                         const float* __restrict__ cov) {
    __shared__ float s_red[8];
    __shared__ int   s_oki[8];
    __shared__ float s_inv[DIMS];
    __shared__ int   s_flag;
    int tid = threadIdx.x;
    int lane = tid & 31, w = tid >> 5;

    float a = (tid < KCOMP) ? alpha[tid] : -3.0e38f;

    // warp+block max via shuffles (2 rounds)
    float mx = a;
    #pragma unroll
    for (int o = 16; o > 0; o >>= 1) mx = fmaxf(mx, __shfl_xor_sync(0xffffffffu, mx, o));
    if (lane == 0) s_red[w] = mx;
    __syncthreads();
    float amax;
    {
        float t = s_red[lane & 7];
        #pragma unroll
        for (int o = 4; o > 0; o >>= 1) t = fmaxf(t, __shfl_xor_sync(0xffffffffu, t, o));
        amax = t;
    }
    __syncthreads();

    float e = (tid < KCOMP) ? __expf(a - amax) : 0.0f;
    float sm = e;
    #pragma unroll
    for (int o = 16; o > 0; o >>= 1) sm += __shfl_xor_sync(0xffffffffu, sm, o);
    if (lane == 0) s_red[w] = sm;
    __syncthreads();
    float sum;
    {
        float t = s_red[lane & 7];
        #pragma unroll
        for (int o = 4; o > 0; o >>= 1) t += __shfl_xor_sync(0xffffffffu, t, o);
        sum = t;
    }

    // uniform-cov check (bitwise vs row 0)
    int ok = 1;
    if (tid < KCOMP) {
        #pragma unroll 4
        for (int d = 0; d < DIMS; ++d)
            ok &= (__float_as_int(cov[tid * DIMS + d]) == __float_as_int(cov[d]));
    }
    ok = __all_sync(0xffffffffu, ok);
    if (lane == 0) s_oki[w] = ok;
    __syncthreads();
    if (tid == 0) {
        int f = 1;
        #pragma unroll
        for (int i = 0; i < 8; ++i) f &= s_oki[i];
        s_flag = f;
        g_flag = f;
    }
    if (tid < DIMS) s_inv[tid] = 1.0f / cov[tid];   // row-0 inverses
    __syncthreads();

    float logw = (tid < KCOMP) ? (a - amax - __logf(sum)) : 0.0f;
    int flag = s_flag;

    if (tid < KCOMP) {
        int k = tid;
        int i = k / MULTK;
        float lsig = 0.5f * (float)(DIMS - i) * 2.302585092994046f;
        float cacc = logw + lsig;
        if (flag) {
            #pragma unroll
            for (int d = 0; d < DIMS; ++d) {
                float inv = s_inv[d];
                float m = mu[k * DIMS + d];
                float w1 = m * inv * LOG2E;
                if (k == 0) g_w2c[d] = -0.5f * inv * LOG2E;
                __nv_bfloat16 h = __float2bfloat16_rn(w1);
                float lo = w1 - __bfloat162float(h);
                __nv_bfloat16 l = __float2bfloat16_rn(lo);
                g_B[k * KF + d]            = __bfloat16_as_ushort(h);   // pairs x_hi
                g_B[k * KF + DIMS + d]     = __bfloat16_as_ushort(l);   // pairs x_hi
                g_B[k * KF + 2 * DIMS + d] = __bfloat16_as_ushort(h);   // pairs x_lo
                cacc -= 0.5f * m * m * inv;
            }
            #pragma unroll
            for (int c = 3 * DIMS; c < KF; ++c) g_B[k * KF + c] = 0;
        } else {
            // dormant general path: full per-(k,d) divisions
            for (int d = 0; d < DIMS; ++d) {
                float inv = 1.0f / cov[k * DIMS + d];
                float m = mu[k * DIMS + d];
                g_Wg[k * 2 * DIMS + d]        = -0.5f * inv * LOG2E;
                g_Wg[k * 2 * DIMS + DIMS + d] = m * inv * LOG2E;
                cacc -= 0.5f * m * m * inv;
            }
        }
        g_c[k] = cacc * LOG2E;
    }
}

// ---------------- main: mma.sync bf16 fast path + inline scalar fallback ----------------
__global__ __launch_bounds__(TPB) void gmm_tensor(const float* __restrict__ sample,
                                                  float* __restrict__ out,
                                                  int n_total) {
    __shared__ __align__(16) unsigned short sA[TILE_M * AS];   // 18432 B
    __shared__ __align__(16) unsigned short sB[KCOMP * AS];    // 24192 B
    __shared__ float s_sc[KCOMP];
    __shared__ float s_w2[DIMS];
    __shared__ float s_q2[TILE_M];

    int tid  = threadIdx.x;
    int wid  = tid >> 5;
    int lane = tid & 31;

    if (g_flag == 0) {
        // ---- scalar fallback inline (non-uniform cov; dormant in practice) ----
        float* sW = (float*)sB;   // 168*40*4 = 26880 <= 24192+18432 contiguous? use sA+sB region
        // sB alone is 24192 B < 26880; use sA (18432) for the overflow-free simple route:
        // just read g_Wg straight from global (L2-resident, dormant path).
        for (int i = tid; i < KCOMP; i += TPB) s_sc[i] = g_c[i];
        __syncthreads();
        (void)sW;
        int n = blockIdx.x * TILE_M + tid;
        if (n < n_total) {
            float x[DIMS];
            const float4* xp = (const float4*)(sample + (size_t)n * DIMS);
            #pragma unroll
            for (int j = 0; j < 5; ++j) {
                float4 v = xp[j];
                x[4*j+0]=v.x; x[4*j+1]=v.y; x[4*j+2]=v.z; x[4*j+3]=v.w;
            }
            float dens = 0.0f;
            for (int k = 0; k < KCOMP; ++k) {
                const float* wr = g_Wg + k * 2 * DIMS;
                float e = s_sc[k];
                #pragma unroll
                for (int d = 0; d < DIMS; ++d)
                    e = fmaf(wr[d] * x[d], x[d], fmaf(wr[DIMS + d], x[d], e));
                dens += ex2f(e);
            }
            out[n] = lg2f(dens) * LN2 + LOGNRM;
        }
        return;
    }

    // ---- stage B, sc, w2c ----
    {
        const unsigned* Bsrc = (const unsigned*)g_B;   // rows of 32 u32
        for (int i = tid; i < KCOMP * (KF / 2); i += TPB) {
            int row = i >> 5, c = i & 31;
            ((unsigned*)sB)[row * (AS / 2) + c] = Bsrc[i];
        }
        for (int i = tid; i < KCOMP; i += TPB) s_sc[i] = g_c[i];
        if (tid < DIMS) s_w2[tid] = g_w2c[tid];
    }
    __syncthreads();   // s_w2 ready (needed for q2 below)

    // ---- load sample row, q2, stage A (bf16 2-way split) ----
    int n = blockIdx.x * TILE_M + tid;
    int m = min(n, n_total - 1);
    float x[DIMS];
    {
        const float4* xp = (const float4*)(sample + (size_t)m * DIMS);
        #pragma unroll
        for (int j = 0; j < 5; ++j) {
            float4 v = xp[j];
            x[4*j+0] = v.x; x[4*j+1] = v.y; x[4*j+2] = v.z; x[4*j+3] = v.w;
        }
    }
    {
        float q2 = 0.0f;
        #pragma unroll
        for (int d = 0; d < DIMS; ++d) q2 = fmaf(s_w2[d] * x[d], x[d], q2);
        s_q2[tid] = q2;
    }
    {
        unsigned* Arow = (unsigned*)sA + tid * (AS / 2);
        #pragma unroll
        for (int j = 0; j < 10; ++j) {
            __nv_bfloat16 h0 = __float2bfloat16_rn(x[2*j]);
            __nv_bfloat16 h1 = __float2bfloat16_rn(x[2*j+1]);
            float r0 = x[2*j]   - __bfloat162float(h0);
            float r1 = x[2*j+1] - __bfloat162float(h1);
            __nv_bfloat16 l0 = __float2bfloat16_rn(r0);
            __nv_bfloat16 l1 = __float2bfloat16_rn(r1);
            unsigned hh = (unsigned)__bfloat16_as_ushort(h0) | ((unsigned)__bfloat16_as_ushort(h1) << 16);
            unsigned ll = (unsigned)__bfloat16_as_ushort(l0) | ((unsigned)__bfloat16_as_ushort(l1) << 16);
            Arow[j] = hh; Arow[10 + j] = hh; Arow[20 + j] = ll;
        }
        Arow[30] = 0u; Arow[31] = 0u;
    }
    __syncthreads();   // A + q2 ready

    unsigned sAu = smem_u32(sA);
    unsigned sBu = smem_u32(sB);

    // ---- A fragments for this warp's 2 m-tiles (rows wid*32 .. +31) ----
    int lr = lane & 7;           // row within 8x8 tile
    int tI = lane >> 3;          // tile index 0..3
    int arow_off = lr + (tI & 1) * 8;
    int akcol_off = (tI >> 1) * 8;

    unsigned aF0[16], aF1[16];   // [ks][4]
    int R0 = wid * 32;
    #pragma unroll
    for (int ks = 0; ks < 4; ++ks) {
        unsigned ad0 = sAu + (unsigned)((R0 + arow_off) * AS + ks * 16 + akcol_off) * 2u;
        unsigned ad1 = sAu + (unsigned)((R0 + 16 + arow_off) * AS + ks * 16 + akcol_off) * 2u;
        ldsm_x4(aF0[4*ks], aF0[4*ks+1], aF0[4*ks+2], aF0[4*ks+3], ad0);
        ldsm_x4(aF1[4*ks], aF1[4*ks+1], aF1[4*ks+2], aF1[4*ks+3], ad1);
    }

    float dl0 = 0.f, dh0 = 0.f, dl1 = 0.f, dh1 = 0.f;
    int t4 = lane & 3;

    #pragma unroll 3
    for (int nb = 0; nb < NTILES; ++nb) {
        unsigned b[8];
        unsigned brow = (unsigned)(8 * nb + lr) * AS;
        ldsm_x4(b[0], b[1], b[2], b[3], sBu + (brow + (unsigned)tI * 8u) * 2u);
        ldsm_x4(b[4], b[5], b[6], b[7], sBu + (brow + 32u + (unsigned)tI * 8u) * 2u);

        float a0[4] = {0.f, 0.f, 0.f, 0.f};
        float a1[4] = {0.f, 0.f, 0.f, 0.f};
        #pragma unroll
        for (int ks = 0; ks < 4; ++ks) {
            mma16816(a0, &aF0[4*ks], b[2*ks], b[2*ks+1]);
            mma16816(a1, &aF1[4*ks], b[2*ks], b[2*ks+1]);
        }
        float c0 = s_sc[nb * 8 + 2 * t4];
        float c1 = s_sc[nb * 8 + 2 * t4 + 1];
        dl0 += ex2f(a0[0] + c0) + ex2f(a0[1] + c1);
        dh0 += ex2f(a0[2] + c0) + ex2f(a0[3] + c1);
        dl1 += ex2f(a1[0] + c0) + ex2f(a1[1] + c1);
        dh1 += ex2f(a1[2] + c0) + ex2f(a1[3] + c1);
    }

    // quad reduce (cols of a row live on lanes with same lane/4)
    #pragma unroll
    for (int msk = 1; msk <= 2; msk <<= 1) {
        dl0 += __shfl_xor_sync(0xffffffffu, dl0, msk);
        dh0 += __shfl_xor_sync(0xffffffffu, dh0, msk);
        dl1 += __shfl_xor_sync(0xffffffffu, dl1, msk);
        dh1 += __shfl_xor_sync(0xffffffffu, dh1, msk);
    }

    if (t4 == 0) {
        int g = lane >> 2;
        int base = blockIdx.x * TILE_M;
        int r0 = R0 + g, r1 = R0 + 8 + g, r2 = R0 + 16 + g, r3 = R0 + 24 + g;
        if (base + r0 < n_total) out[base + r0] = (lg2f(dl0) + s_q2[r0]) * LN2 + LOGNRM;
        if (base + r1 < n_total) out[base + r1] = (lg2f(dh0) + s_q2[r1]) * LN2 + LOGNRM;
        if (base + r2 < n_total) out[base + r2] = (lg2f(dl1) + s_q2[r2]) * LN2 + LOGNRM;
        if (base + r3 < n_total) out[base + r3] = (lg2f(dh1) + s_q2[r3]) * LN2 + LOGNRM;
    }
}

extern "C" void kernel_launch(void* const* d_in, const int* in_sizes, int n_in,
                              void* d_out, int out_size) {
    const float* sample = (const float*)d_in[0];
    const float* alpha  = (const float*)d_in[1];
    const float* mu     = (const float*)d_in[2];
    const float* cov    = (const float*)d_in[3];
    float* out = (float*)d_out;
    int n_total = in_sizes[0] / DIMS;
    int ntiles = (n_total + TILE_M - 1) / TILE_M;

    gmm_prep<<<1, 256>>>(alpha, mu, cov);
    gmm_tensor<<<ntiles, TPB>>>(sample, out, n_total);
}

// round 10
// speedup vs baseline: 4.7075x; 1.3450x over previous
#include <cuda_runtime.h>
#include <cuda_bf16.h>
#include <math.h>

#define DIMS   20
#define MULTK  8
#define KCOMP  168
#define LOG2E  1.4426950408889634f
#define LN2    0.6931471805599453f
#define LOGNRM (-18.378770664093453f)   // -(DIMS/2)*log(2*pi)

#define TILE_M 128
#define KF     64          // GEMM K: [x_hi(20) | x_hi(20) | x_lo(20) | 0(4)]
#define NTILES 21          // 168 / 8 components per n-tile
#define TPB    128
#define AS     72          // smem row stride in bf16 (144B -> conflict-free ldmatrix)

// prep outputs
__device__ __align__(16) unsigned g_Bf[NTILES * 8 * 32];  // B in mma fragment order [nb][t][lane]
__device__ float g_c[KCOMP];              // log2-domain constant per component
__device__ float g_w2c[DIMS];             // common x^2 coeff row (-0.5*inv*log2e)
__device__ float g_Wg[KCOMP * 2 * DIMS];  // fallback coeffs (log2-domain)
__device__ int   g_flag;                  // 1 if cov rows identical across k

// ---------------- helpers ----------------
__device__ __forceinline__ float ex2f(float x) { float r; asm("ex2.approx.f32 %0, %1;" : "=f"(r) : "f"(x)); return r; }
__device__ __forceinline__ float lg2f(float x) { float r; asm("lg2.approx.f32 %0, %1;" : "=f"(r) : "f"(x)); return r; }
__device__ __forceinline__ unsigned smem_u32(const void* p) {
    unsigned a;
    asm("{ .reg .u64 t; cvta.to.shared.u64 t, %1; cvt.u32.u64 %0, t; }" : "=r"(a) : "l"(p));
    return a;
}
__device__ __forceinline__ void ldsm_x4(unsigned& r0, unsigned& r1, unsigned& r2, unsigned& r3, unsigned addr) {
    asm volatile("ldmatrix.sync.aligned.m8n8.x4.shared.b16 {%0,%1,%2,%3}, [%4];"
                 : "=r"(r0), "=r"(r1), "=r"(r2), "=r"(r3) : "r"(addr));
}
__device__ __forceinline__ void mma16816(float* d, const unsigned* a, unsigned b0, unsigned b1) {
    asm volatile("mma.sync.aligned.m16n8k16.row.col.f32.bf16.bf16.f32 "
                 "{%0,%1,%2,%3}, {%4,%5,%6,%7}, {%8,%9}, {%0,%1,%2,%3};"
                 : "+f"(d[0]), "+f"(d[1]), "+f"(d[2]), "+f"(d[3])
                 : "r"(a[0]), "r"(a[1]), "r"(a[2]), "r"(a[3]), "r"(b0), "r"(b1));
}

// ---------------- prep: fast softmax + fragment-ordered B (1 block, 256 thr) ----------------
__global__ void gmm_prep(const float* __restrict__ alpha,
                         const float* __restrict__ mu,
                         const float* __restrict__ cov) {
    __shared__ float s_red[8];
    __shared__ int   s_oki[8];
    __shared__ float s_inv[DIMS];
    __shared__ int   s_flag;
    int tid = threadIdx.x;
    int lane = tid & 31, w = tid >> 5;

    float a = (tid < KCOMP) ? alpha[tid] : -3.0e38f;

    // block max via shuffles
    float mx = a;
    #pragma unroll
    for (int o = 16; o > 0; o >>= 1) mx = fmaxf(mx, __shfl_xor_sync(0xffffffffu, mx, o));
    if (lane == 0) s_red[w] = mx;
    __syncthreads();
    float amax;
    {
        float t = s_red[lane & 7];
        #pragma unroll
        for (int o = 4; o > 0; o >>= 1) t = fmaxf(t, __shfl_xor_sync(0xffffffffu, t, o));
        amax = t;
    }
    __syncthreads();

    float e = (tid < KCOMP) ? __expf(a - amax) : 0.0f;
    float sm = e;
    #pragma unroll
    for (int o = 16; o > 0; o >>= 1) sm += __shfl_xor_sync(0xffffffffu, sm, o);
    if (lane == 0) s_red[w] = sm;
    __syncthreads();
    float sum;
    {
        float t = s_red[lane & 7];
        #pragma unroll
        for (int o = 4; o > 0; o >>= 1) t += __shfl_xor_sync(0xffffffffu, t, o);
        sum = t;
    }

    // uniform-cov check (bitwise vs row 0)
    int ok = 1;
    if (tid < KCOMP) {
        #pragma unroll 4
        for (int d = 0; d < DIMS; ++d)
            ok &= (__float_as_int(cov[tid * DIMS + d]) == __float_as_int(cov[d]));
    }
    ok = __all_sync(0xffffffffu, ok);
    if (lane == 0) s_oki[w] = ok;
    __syncthreads();
    if (tid == 0) {
        int f = 1;
        #pragma unroll
        for (int i = 0; i < 8; ++i) f &= s_oki[i];
        s_flag = f;
        g_flag = f;
    }
    if (tid < DIMS) s_inv[tid] = 1.0f / cov[tid];   // row-0 inverses
    __syncthreads();

    float logw = (tid < KCOMP) ? (a - amax - __logf(sum)) : 0.0f;
    int flag = s_flag;

    if (tid < KCOMP) {
        int k = tid;
        int i = k / MULTK;
        float lsig = 0.5f * (float)(DIMS - i) * 2.302585092994046f;
        float cacc = logw + lsig;
        if (flag) {
            unsigned short rowW[KF];
            #pragma unroll
            for (int c = 0; c < KF; ++c) rowW[c] = 0;
            #pragma unroll
            for (int d = 0; d < DIMS; ++d) {
                float inv = s_inv[d];
                float m = mu[k * DIMS + d];
                float w1 = m * inv * LOG2E;
                if (k == 0) g_w2c[d] = -0.5f * inv * LOG2E;
                __nv_bfloat16 h = __float2bfloat16_rn(w1);
                float lo = w1 - __bfloat162float(h);
                __nv_bfloat16 l = __float2bfloat16_rn(lo);
                rowW[d]            = __bfloat16_as_ushort(h);   // pairs x_hi
                rowW[DIMS + d]     = __bfloat16_as_ushort(l);   // pairs x_hi
                rowW[2 * DIMS + d] = __bfloat16_as_ushort(h);   // pairs x_lo
                cacc -= 0.5f * m * m * inv;
            }
            // scatter into fragment order: lane l of chunk t holds
            // W[8nb + (l>>2)][t*8 + (l&3)*2 + {0,1}]
            int nb = k >> 3, r8 = k & 7;
            #pragma unroll
            for (int t = 0; t < 8; ++t) {
                #pragma unroll
                for (int q = 0; q < 4; ++q) {
                    unsigned v = (unsigned)rowW[t * 8 + 2 * q] |
                                 ((unsigned)rowW[t * 8 + 2 * q + 1] << 16);
                    g_Bf[(nb * 8 + t) * 32 + r8 * 4 + q] = v;
                }
            }
        } else {
            // dormant general path
            for (int d = 0; d < DIMS; ++d) {
                float inv = 1.0f / cov[k * DIMS + d];
                float m = mu[k * DIMS + d];
                g_Wg[k * 2 * DIMS + d]        = -0.5f * inv * LOG2E;
                g_Wg[k * 2 * DIMS + DIMS + d] = m * inv * LOG2E;
                cacc -= 0.5f * m * m * inv;
            }
        }
        g_c[k] = cacc * LOG2E;
    }
}

// ---------------- main: mma.sync bf16 fast path + inline scalar fallback ----------------
__global__ __launch_bounds__(TPB) void gmm_tensor(const float* __restrict__ sample,
                                                  float* __restrict__ out,
                                                  int n_total) {
    __shared__ __align__(16) unsigned short sA[TILE_M * AS];   // 18432 B
    __shared__ float s_sc[KCOMP];
    __shared__ float s_w2[DIMS];
    __shared__ float s_q2[TILE_M];

    int tid  = threadIdx.x;
    int wid  = tid >> 5;
    int lane = tid & 31;

    if (g_flag == 0) {
        // ---- scalar fallback (non-uniform cov; dormant in practice) ----
        for (int i = tid; i < KCOMP; i += TPB) s_sc[i] = g_c[i];
        __syncthreads();
        int n = blockIdx.x * TILE_M + tid;
        if (n < n_total) {
            float x[DIMS];
            const float4* xp = (const float4*)(sample + (size_t)n * DIMS);
            #pragma unroll
            for (int j = 0; j < 5; ++j) {
                float4 v = xp[j];
                x[4*j+0]=v.x; x[4*j+1]=v.y; x[4*j+2]=v.z; x[4*j+3]=v.w;
            }
            float dens = 0.0f;
            for (int k = 0; k < KCOMP; ++k) {
                const float* wr = g_Wg + k * 2 * DIMS;
                float e = s_sc[k];
                #pragma unroll
                for (int d = 0; d < DIMS; ++d)
                    e = fmaf(wr[d] * x[d], x[d], fmaf(wr[DIMS + d], x[d], e));
                dens += ex2f(e);
            }
            out[n] = lg2f(dens) * LN2 + LOGNRM;
        }
        return;
    }

    // ---- stage sc, w2c ----
    for (int i = tid; i < KCOMP; i += TPB) s_sc[i] = g_c[i];
    if (tid < DIMS) s_w2[tid] = g_w2c[tid];
    __syncthreads();   // s_w2 ready

    // ---- load sample row, q2, stage A (bf16 2-way split) ----
    int n = blockIdx.x * TILE_M + tid;
    int m = min(n, n_total - 1);
    float x[DIMS];
    {
        const float4* xp = (const float4*)(sample + (size_t)m * DIMS);
        #pragma unroll
        for (int j = 0; j < 5; ++j) {
            float4 v = xp[j];
            x[4*j+0] = v.x; x[4*j+1] = v.y; x[4*j+2] = v.z; x[4*j+3] = v.w;
        }
    }
    {
        float q2 = 0.0f;
        #pragma unroll
        for (int d = 0; d < DIMS; ++d) q2 = fmaf(s_w2[d] * x[d], x[d], q2);
        s_q2[tid] = q2;
    }
    {
        unsigned* Arow = (unsigned*)sA + tid * (AS / 2);
        #pragma unroll
        for (int j = 0; j < 10; ++j) {
            __nv_bfloat16 h0 = __float2bfloat16_rn(x[2*j]);
            __nv_bfloat16 h1 = __float2bfloat16_rn(x[2*j+1]);
            float r0 = x[2*j]   - __bfloat162float(h0);
            float r1 = x[2*j+1] - __bfloat162float(h1);
            __nv_bfloat16 l0 = __float2bfloat16_rn(r0);
            __nv_bfloat16 l1 = __float2bfloat16_rn(r1);
            unsigned hh = (unsigned)__bfloat16_as_ushort(h0) | ((unsigned)__bfloat16_as_ushort(h1) << 16);
            unsigned ll = (unsigned)__bfloat16_as_ushort(l0) | ((unsigned)__bfloat16_as_ushort(l1) << 16);
            Arow[j] = hh; Arow[10 + j] = hh; Arow[20 + j] = ll;
        }
        Arow[30] = 0u; Arow[31] = 0u;
    }
    __syncthreads();   // A + q2 ready

    unsigned sAu = smem_u32(sA);

    // ---- A fragments for this warp's 2 m-tiles (rows wid*32 .. +31) ----
    int lr = lane & 7;           // row within 8x8 tile
    int tI = lane >> 3;          // tile index 0..3
    int arow_off = lr + (tI & 1) * 8;
    int akcol_off = (tI >> 1) * 8;

    unsigned aF0[16], aF1[16];   // [ks][4]
    int R0 = wid * 32;
    #pragma unroll
    for (int ks = 0; ks < 4; ++ks) {
        unsigned ad0 = sAu + (unsigned)((R0 + arow_off) * AS + ks * 16 + akcol_off) * 2u;
        unsigned ad1 = sAu + (unsigned)((R0 + 16 + arow_off) * AS + ks * 16 + akcol_off) * 2u;
        ldsm_x4(aF0[4*ks], aF0[4*ks+1], aF0[4*ks+2], aF0[4*ks+3], ad0);
        ldsm_x4(aF1[4*ks], aF1[4*ks+1], aF1[4*ks+2], aF1[4*ks+3], ad1);
    }

    float dl0 = 0.f, dh0 = 0.f, dl1 = 0.f, dh1 = 0.f;
    int t4 = lane & 3;
    const unsigned* __restrict__ Bf = g_Bf;

    #pragma unroll 3
    for (int nb = 0; nb < NTILES; ++nb) {
        // B fragments: direct coalesced loads, already in mma order
        unsigned b[8];
        #pragma unroll
        for (int t = 0; t < 8; ++t)
            b[t] = __ldg(Bf + (nb * 8 + t) * 32 + lane);

        float a0[4] = {0.f, 0.f, 0.f, 0.f};
        float a1[4] = {0.f, 0.f, 0.f, 0.f};
        #pragma unroll
        for (int ks = 0; ks < 4; ++ks) {
            mma16816(a0, &aF0[4*ks], b[2*ks], b[2*ks+1]);
            mma16816(a1, &aF1[4*ks], b[2*ks], b[2*ks+1]);
        }
        float c0 = s_sc[nb * 8 + 2 * t4];
        float c1 = s_sc[nb * 8 + 2 * t4 + 1];
        dl0 += ex2f(a0[0] + c0) + ex2f(a0[1] + c1);
        dh0 += ex2f(a0[2] + c0) + ex2f(a0[3] + c1);
        dl1 += ex2f(a1[0] + c0) + ex2f(a1[1] + c1);
        dh1 += ex2f(a1[2] + c0) + ex2f(a1[3] + c1);
    }

    // quad reduce (cols of a row live on lanes with same lane/4)
    #pragma unroll
    for (int msk = 1; msk <= 2; msk <<= 1) {
        dl0 += __shfl_xor_sync(0xffffffffu, dl0, msk);
        dh0 += __shfl_xor_sync(0xffffffffu, dh0, msk);
        dl1 += __shfl_xor_sync(0xffffffffu, dl1, msk);
        dh1 += __shfl_xor_sync(0xffffffffu, dh1, msk);
    }

    if (t4 == 0) {
        int g = lane >> 2;
        int base = blockIdx.x * TILE_M;
        int r0 = R0 + g, r1 = R0 + 8 + g, r2 = R0 + 16 + g, r3 = R0 + 24 + g;
        if (base + r0 < n_total) out[base + r0] = (lg2f(dl0) + s_q2[r0]) * LN2 + LOGNRM;
        if (base + r1 < n_total) out[base + r1] = (lg2f(dh0) + s_q2[r1]) * LN2 + LOGNRM;
        if (base + r2 < n_total) out[base + r2] = (lg2f(dl1) + s_q2[r2]) * LN2 + LOGNRM;
        if (base + r3 < n_total) out[base + r3] = (lg2f(dh1) + s_q2[r3]) * LN2 + LOGNRM;
    }
}

extern "C" void kernel_launch(void* const* d_in, const int* in_sizes, int n_in,
                              void* d_out, int out_size) {
    const float* sample = (const float*)d_in[0];
    const float* alpha  = (const float*)d_in[1];
    const float* mu     = (const float*)d_in[2];
    const float* cov    = (const float*)d_in[3];
    float* out = (float*)d_out;
    int n_total = in_sizes[0] / DIMS;
    int ntiles = (n_total + TILE_M - 1) / TILE_M;

    gmm_prep<<<1, 256>>>(alpha, mu, cov);
    gmm_tensor<<<ntiles, TPB>>>(sample, out, n_total);
}

// round 11
// speedup vs baseline: 4.7522x; 1.0095x over previous
#include <cuda_runtime.h>
#include <cuda_bf16.h>
#include <math.h>

#define DIMS   20
#define MULTK  8
#define KCOMP  168
#define LOG2E  1.4426950408889634f
#define LN2    0.6931471805599453f
#define LOGNRM (-18.378770664093453f)   // -(DIMS/2)*log(2*pi)

#define TILE_M 128
#define KF     64          // GEMM K: [x_hi(20) | x_hi(20) | x_lo(20) | 0(4)]
#define NTILES 21          // 168 / 8 components per n-tile
#define TPB    128
#define AS     72          // smem row stride in bf16 (144B -> conflict-free ldmatrix)

// prep outputs
// B in per-lane-contiguous fragment order: g_Bf[(nb*32 + lane)*8 + t]
__device__ __align__(16) unsigned g_Bf[NTILES * 32 * 8];
__device__ float g_c[KCOMP];              // log2-domain constant per component
__device__ float g_w2c[DIMS];             // common x^2 coeff row (-0.5*inv*log2e)
__device__ float g_Wg[KCOMP * 2 * DIMS];  // fallback coeffs (log2-domain)
__device__ int   g_flag;                  // 1 if cov rows identical across k

// ---------------- helpers ----------------
__device__ __forceinline__ float ex2f(float x) { float r; asm("ex2.approx.f32 %0, %1;" : "=f"(r) : "f"(x)); return r; }
__device__ __forceinline__ float lg2f(float x) { float r; asm("lg2.approx.f32 %0, %1;" : "=f"(r) : "f"(x)); return r; }
__device__ __forceinline__ unsigned smem_u32(const void* p) {
    unsigned a;
    asm("{ .reg .u64 t; cvta.to.shared.u64 t, %1; cvt.u32.u64 %0, t; }" : "=r"(a) : "l"(p));
    return a;
}
__device__ __forceinline__ void ldsm_x4(unsigned& r0, unsigned& r1, unsigned& r2, unsigned& r3, unsigned addr) {
    asm volatile("ldmatrix.sync.aligned.m8n8.x4.shared.b16 {%0,%1,%2,%3}, [%4];"
                 : "=r"(r0), "=r"(r1), "=r"(r2), "=r"(r3) : "r"(addr));
}
__device__ __forceinline__ void mma16816(float* d, const unsigned* a, unsigned b0, unsigned b1) {
    asm volatile("mma.sync.aligned.m16n8k16.row.col.f32.bf16.bf16.f32 "
                 "{%0,%1,%2,%3}, {%4,%5,%6,%7}, {%8,%9}, {%0,%1,%2,%3};"
                 : "+f"(d[0]), "+f"(d[1]), "+f"(d[2]), "+f"(d[3])
                 : "r"(a[0]), "r"(a[1]), "r"(a[2]), "r"(a[3]), "r"(b0), "r"(b1));
}

// ---------------- prep: fast softmax + fragment-ordered B (1 block, 256 thr) ----------------
__global__ void gmm_prep(const float* __restrict__ alpha,
                         const float* __restrict__ mu,
                         const float* __restrict__ cov) {
    __shared__ float s_red[8];
    __shared__ int   s_oki[8];
    __shared__ float s_inv[DIMS];
    __shared__ int   s_flag;
    int tid = threadIdx.x;
    int lane = tid & 31, w = tid >> 5;

    float a = (tid < KCOMP) ? alpha[tid] : -3.0e38f;

    // block max via shuffles
    float mx = a;
    #pragma unroll
    for (int o = 16; o > 0; o >>= 1) mx = fmaxf(mx, __shfl_xor_sync(0xffffffffu, mx, o));
    if (lane == 0) s_red[w] = mx;
    __syncthreads();
    float amax;
    {
        float t = s_red[lane & 7];
        #pragma unroll
        for (int o = 4; o > 0; o >>= 1) t = fmaxf(t, __shfl_xor_sync(0xffffffffu, t, o));
        amax = t;
    }
    __syncthreads();

    float e = (tid < KCOMP) ? __expf(a - amax) : 0.0f;
    float sm = e;
    #pragma unroll
    for (int o = 16; o > 0; o >>= 1) sm += __shfl_xor_sync(0xffffffffu, sm, o);
    if (lane == 0) s_red[w] = sm;
    __syncthreads();
    float sum;
    {
        float t = s_red[lane & 7];
        #pragma unroll
        for (int o = 4; o > 0; o >>= 1) t += __shfl_xor_sync(0xffffffffu, t, o);
        sum = t;
    }

    // uniform-cov check (bitwise vs row 0)
    int ok = 1;
    if (tid < KCOMP) {
        #pragma unroll 4
        for (int d = 0; d < DIMS; ++d)
            ok &= (__float_as_int(cov[tid * DIMS + d]) == __float_as_int(cov[d]));
    }
    ok = __all_sync(0xffffffffu, ok);
    if (lane == 0) s_oki[w] = ok;
    __syncthreads();
    if (tid == 0) {
        int f = 1;
        #pragma unroll
        for (int i = 0; i < 8; ++i) f &= s_oki[i];
        s_flag = f;
        g_flag = f;
    }
    if (tid < DIMS) s_inv[tid] = 1.0f / cov[tid];   // row-0 inverses
    __syncthreads();

    float logw = (tid < KCOMP) ? (a - amax - __logf(sum)) : 0.0f;
    int flag = s_flag;

    if (tid < KCOMP) {
        int k = tid;
        int i = k / MULTK;
        float lsig = 0.5f * (float)(DIMS - i) * 2.302585092994046f;
        float cacc = logw + lsig;
        if (flag) {
            unsigned short rowW[KF];
            #pragma unroll
            for (int c = 0; c < KF; ++c) rowW[c] = 0;
            #pragma unroll
            for (int d = 0; d < DIMS; ++d) {
                float inv = s_inv[d];
                float m = mu[k * DIMS + d];
                float w1 = m * inv * LOG2E;
                if (k == 0) g_w2c[d] = -0.5f * inv * LOG2E;
                __nv_bfloat16 h = __float2bfloat16_rn(w1);
                float lo = w1 - __bfloat162float(h);
                __nv_bfloat16 l = __float2bfloat16_rn(lo);
                rowW[d]            = __bfloat16_as_ushort(h);   // pairs x_hi
                rowW[DIMS + d]     = __bfloat16_as_ushort(l);   // pairs x_hi
                rowW[2 * DIMS + d] = __bfloat16_as_ushort(h);   // pairs x_lo
                cacc -= 0.5f * m * m * inv;
            }
            // scatter into per-lane fragment order: lane l = r8*4+q of chunk t holds
            // W[8nb + r8][t*8 + q*2 + {0,1}]; layout g_Bf[(nb*32 + l)*8 + t]
            int nb = k >> 3, r8 = k & 7;
            #pragma unroll
            for (int t = 0; t < 8; ++t) {
                #pragma unroll
                for (int q = 0; q < 4; ++q) {
                    unsigned v = (unsigned)rowW[t * 8 + 2 * q] |
                                 ((unsigned)rowW[t * 8 + 2 * q + 1] << 16);
                    g_Bf[(nb * 32 + r8 * 4 + q) * 8 + t] = v;
                }
            }
        } else {
            // dormant general path
            for (int d = 0; d < DIMS; ++d) {
                float inv = 1.0f / cov[k * DIMS + d];
                float m = mu[k * DIMS + d];
                g_Wg[k * 2 * DIMS + d]        = -0.5f * inv * LOG2E;
                g_Wg[k * 2 * DIMS + DIMS + d] = m * inv * LOG2E;
                cacc -= 0.5f * m * m * inv;
            }
        }
        g_c[k] = cacc * LOG2E;
    }
}

// ---------------- main: mma.sync bf16 fast path + inline scalar fallback ----------------
__global__ __launch_bounds__(TPB) void gmm_tensor(const float* __restrict__ sample,
                                                  float* __restrict__ out,
                                                  int n_total) {
    __shared__ __align__(16) unsigned short sA[TILE_M * AS];   // 18432 B
    __shared__ float s_sc[KCOMP];
    __shared__ float s_w2[DIMS];
    __shared__ float s_q2[TILE_M];

    int tid  = threadIdx.x;
    int wid  = tid >> 5;
    int lane = tid & 31;

    if (g_flag == 0) {
        // ---- scalar fallback (non-uniform cov; dormant in practice) ----
        for (int i = tid; i < KCOMP; i += TPB) s_sc[i] = g_c[i];
        __syncthreads();
        int n = blockIdx.x * TILE_M + tid;
        if (n < n_total) {
            float x[DIMS];
            const float4* xp = (const float4*)(sample + (size_t)n * DIMS);
            #pragma unroll
            for (int j = 0; j < 5; ++j) {
                float4 v = xp[j];
                x[4*j+0]=v.x; x[4*j+1]=v.y; x[4*j+2]=v.z; x[4*j+3]=v.w;
            }
            float dens = 0.0f;
            for (int k = 0; k < KCOMP; ++k) {
                const float* wr = g_Wg + k * 2 * DIMS;
                float e = s_sc[k];
                #pragma unroll
                for (int d = 0; d < DIMS; ++d)
                    e = fmaf(wr[d] * x[d], x[d], fmaf(wr[DIMS + d], x[d], e));
                dens += ex2f(e);
            }
            out[n] = lg2f(dens) * LN2 + LOGNRM;
        }
        return;
    }

    // ---- stage sc, w2c ----
    for (int i = tid; i < KCOMP; i += TPB) s_sc[i] = g_c[i];
    if (tid < DIMS) s_w2[tid] = g_w2c[tid];
    __syncthreads();   // s_w2 ready

    // ---- load sample row, q2, stage A (bf16 2-way split) ----
    int n = blockIdx.x * TILE_M + tid;
    int m = min(n, n_total - 1);
    float x[DIMS];
    {
        const float4* xp = (const float4*)(sample + (size_t)m * DIMS);
        #pragma unroll
        for (int j = 0; j < 5; ++j) {
            float4 v = xp[j];
            x[4*j+0] = v.x; x[4*j+1] = v.y; x[4*j+2] = v.z; x[4*j+3] = v.w;
        }
    }
    {
        float q2 = 0.0f;
        #pragma unroll
        for (int d = 0; d < DIMS; ++d) q2 = fmaf(s_w2[d] * x[d], x[d], q2);
        s_q2[tid] = q2;
    }
    {
        unsigned* Arow = (unsigned*)sA + tid * (AS / 2);
        #pragma unroll
        for (int j = 0; j < 10; ++j) {
            __nv_bfloat16 h0 = __float2bfloat16_rn(x[2*j]);
            __nv_bfloat16 h1 = __float2bfloat16_rn(x[2*j+1]);
            float r0 = x[2*j]   - __bfloat162float(h0);
            float r1 = x[2*j+1] - __bfloat162float(h1);
            __nv_bfloat16 l0 = __float2bfloat16_rn(r0);
            __nv_bfloat16 l1 = __float2bfloat16_rn(r1);
            unsigned hh = (unsigned)__bfloat16_as_ushort(h0) | ((unsigned)__bfloat16_as_ushort(h1) << 16);
            unsigned ll = (unsigned)__bfloat16_as_ushort(l0) | ((unsigned)__bfloat16_as_ushort(l1) << 16);
            Arow[j] = hh; Arow[10 + j] = hh; Arow[20 + j] = ll;
        }
        Arow[30] = 0u; Arow[31] = 0u;
    }
    __syncthreads();   // A + q2 ready

    unsigned sAu = smem_u32(sA);

    // ---- A fragments for this warp's 2 m-tiles (rows wid*32 .. +31) ----
    int lr = lane & 7;           // row within 8x8 tile
    int tI = lane >> 3;          // tile index 0..3
    int arow_off = lr + (tI & 1) * 8;
    int akcol_off = (tI >> 1) * 8;

    unsigned aF0[16], aF1[16];   // [ks][4]
    int R0 = wid * 32;
    #pragma unroll
    for (int ks = 0; ks < 4; ++ks) {
        unsigned ad0 = sAu + (unsigned)((R0 + arow_off) * AS + ks * 16 + akcol_off) * 2u;
        unsigned ad1 = sAu + (unsigned)((R0 + 16 + arow_off) * AS + ks * 16 + akcol_off) * 2u;
        ldsm_x4(aF0[4*ks], aF0[4*ks+1], aF0[4*ks+2], aF0[4*ks+3], ad0);
        ldsm_x4(aF1[4*ks], aF1[4*ks+1], aF1[4*ks+2], aF1[4*ks+3], ad1);
    }

    float dl0 = 0.f, dh0 = 0.f, dl1 = 0.f, dh1 = 0.f;
    int t4 = lane & 3;
    const uint4* __restrict__ Bf4 = (const uint4*)g_Bf;

    #pragma unroll 3
    for (int nb = 0; nb < NTILES; ++nb) {
        // B fragments: 2x LDG.128, per-lane contiguous, already in mma order
        uint4 u0 = __ldg(Bf4 + (nb * 32 + lane) * 2);
        uint4 u1 = __ldg(Bf4 + (nb * 32 + lane) * 2 + 1);

        float c0 = s_sc[nb * 8 + 2 * t4];
        float c1 = s_sc[nb * 8 + 2 * t4 + 1];
        // c_k folded into accumulator init (MMA accumulates on top)
        float a0[4] = {c0, c1, c0, c1};
        float a1[4] = {c0, c1, c0, c1};
        mma16816(a0, &aF0[0],  u0.x, u0.y);
        mma16816(a1, &aF1[0],  u0.x, u0.y);
        mma16816(a0, &aF0[4],  u0.z, u0.w);
        mma16816(a1, &aF1[4],  u0.z, u0.w);
        mma16816(a0, &aF0[8],  u1.x, u1.y);
        mma16816(a1, &aF1[8],  u1.x, u1.y);
        mma16816(a0, &aF0[12], u1.z, u1.w);
        mma16816(a1, &aF1[12], u1.z, u1.w);

        dl0 += ex2f(a0[0]) + ex2f(a0[1]);
        dh0 += ex2f(a0[2]) + ex2f(a0[3]);
        dl1 += ex2f(a1[0]) + ex2f(a1[1]);
        dh1 += ex2f(a1[2]) + ex2f(a1[3]);
    }

    // quad reduce (cols of a row live on lanes with same lane/4)
    #pragma unroll
    for (int msk = 1; msk <= 2; msk <<= 1) {
        dl0 += __shfl_xor_sync(0xffffffffu, dl0, msk);
        dh0 += __shfl_xor_sync(0xffffffffu, dh0, msk);
        dl1 += __shfl_xor_sync(0xffffffffu, dl1, msk);
        dh1 += __shfl_xor_sync(0xffffffffu, dh1, msk);
    }

    if (t4 == 0) {
        int g = lane >> 2;
        int base = blockIdx.x * TILE_M;
        int r0 = R0 + g, r1 = R0 + 8 + g, r2 = R0 + 16 + g, r3 = R0 + 24 + g;
        if (base + r0 < n_total) out[base + r0] = (lg2f(dl0) + s_q2[r0]) * LN2 + LOGNRM;
        if (base + r1 < n_total) out[base + r1] = (lg2f(dh0) + s_q2[r1]) * LN2 + LOGNRM;
        if (base + r2 < n_total) out[base + r2] = (lg2f(dl1) + s_q2[r2]) * LN2 + LOGNRM;
        if (base + r3 < n_total) out[base + r3] = (lg2f(dh1) + s_q2[r3]) * LN2 + LOGNRM;
    }
}

extern "C" void kernel_launch(void* const* d_in, const int* in_sizes, int n_in,
                              void* d_out, int out_size) {
    const float* sample = (const float*)d_in[0];
    const float* alpha  = (const float*)d_in[1];
    const float* mu     = (const float*)d_in[2];
    const float* cov    = (const float*)d_in[3];
    float* out = (float*)d_out;
    int n_total = in_sizes[0] / DIMS;
    int ntiles = (n_total + TILE_M - 1) / TILE_M;

    gmm_prep<<<1, 256>>>(alpha, mu, cov);
    gmm_tensor<<<ntiles, TPB>>>(sample, out, n_total);
}